// round 3
// baseline (speedup 1.0000x reference)
#include <cuda_runtime.h>
#include <cstdint>

// Problem shape
#define BDIM   8192
#define DDIM   2048
#define NUNITS 2048

// GEMM tiling
#define TILE_M 128
#define TILE_N 128
#define KC     128                  // int8 K per stage: 128B rows -> XOR-8 swizzle
#define KITERS (DDIM / KC)          // 16
#define STAGES 3
#define TILE_BYTES (TILE_M * KC)    // 16384 per operand
#define STAGE_BYTES (2 * TILE_BYTES)
#define SMEM_TOTAL (STAGES * STAGE_BYTES)   // 98304 per CTA, 2 CTAs/SM

// Scratch (allocation-free rule: __device__ globals)
__device__ __align__(128) int8_t g_A[(size_t)BDIM * DDIM];    // [M, K] K-major
__device__ __align__(128) int8_t g_B[(size_t)NUNITS * DDIM];  // [N, K] K-major (= sign(kernel)^T)

// ============================ PTX helpers ============================

__device__ __forceinline__ uint32_t smem_u32(const void* p) {
    uint32_t a;
    asm("{ .reg .u64 t; cvta.to.shared.u64 t, %1; cvt.u32.u64 %0, t; }" : "=r"(a) : "l"(p));
    return a;
}

__device__ __forceinline__ void cp_async16(uint32_t dst, const void* src) {
    asm volatile("cp.async.cg.shared.global [%0], [%1], 16;" :: "r"(dst), "l"(src) : "memory");
}
#define CP_COMMIT() asm volatile("cp.async.commit_group;" ::: "memory")
#define CP_WAIT(n)  asm volatile("cp.async.wait_group %0;" :: "n"(n) : "memory")

__device__ __forceinline__ void ldm_x4(uint32_t* r, uint32_t addr) {
    asm volatile("ldmatrix.sync.aligned.m8n8.x4.shared.b16 {%0,%1,%2,%3}, [%4];"
                 : "=r"(r[0]), "=r"(r[1]), "=r"(r[2]), "=r"(r[3]) : "r"(addr));
}

__device__ __forceinline__ void mma_s8(int* d, const uint32_t* a, const uint32_t* b) {
    asm volatile(
        "mma.sync.aligned.m16n8k32.row.col.s32.s8.s8.s32 "
        "{%0,%1,%2,%3}, {%4,%5,%6,%7}, {%8,%9}, {%0,%1,%2,%3};"
        : "+r"(d[0]), "+r"(d[1]), "+r"(d[2]), "+r"(d[3])
        : "r"(a[0]), "r"(a[1]), "r"(a[2]), "r"(a[3]), "r"(b[0]), "r"(b[1]));
}

// swizzled byte offset within a [rows][128B] tile for (row r, 16B-chunk c)
__device__ __forceinline__ uint32_t swz(int r, int c) {
    return (uint32_t)(r * 128 + ((c ^ (r & 7)) << 4));
}

// ============================ Convert kernels ============================

// inputs [B, D] fp32 -> g_A [B, D] int8 (+1 / -1). 16 floats -> 16 bytes per thread.
__global__ void sign_a_kernel(const float4* __restrict__ in, int4* __restrict__ out) {
    int i = blockIdx.x * blockDim.x + threadIdx.x;   // one 16-elem group
    const float4* p = in + (size_t)i * 4;
    uint32_t w[4];
#pragma unroll
    for (int j = 0; j < 4; j++) {
        float4 v = p[j];
        uint32_t b0 = (v.x >= 0.f) ? 0x01u : 0xFFu;
        uint32_t b1 = (v.y >= 0.f) ? 0x01u : 0xFFu;
        uint32_t b2 = (v.z >= 0.f) ? 0x01u : 0xFFu;
        uint32_t b3 = (v.w >= 0.f) ? 0x01u : 0xFFu;
        w[j] = b0 | (b1 << 8) | (b2 << 16) | (b3 << 24);
    }
    out[i] = make_int4((int)w[0], (int)w[1], (int)w[2], (int)w[3]);
}

// kernel [D, UNITS] fp32 row-major -> g_B [UNITS, D] int8 (transposed sign)
__global__ void sign_bt_kernel(const float* __restrict__ kern, int8_t* __restrict__ bt) {
    __shared__ int8_t tile[32][36];
    int n0 = blockIdx.x * 32, k0 = blockIdx.y * 32;
    int tx = threadIdx.x, ty = threadIdx.y;           // (32, 8)
#pragma unroll
    for (int j = 0; j < 4; j++) {
        int kk = k0 + ty + j * 8;
        float v = kern[(size_t)kk * NUNITS + n0 + tx];
        tile[ty + j * 8][tx] = (v >= 0.f) ? (int8_t)1 : (int8_t)-1;   // tile[k][n]
    }
    __syncthreads();
    int tid = ty * 32 + tx;
    int nloc = tid >> 3;           // 0..31
    int kgrp = tid & 7;            // 0..7 (4 bytes each)
    uint32_t w = 0;
#pragma unroll
    for (int b = 0; b < 4; b++)
        w |= ((uint32_t)(uint8_t)tile[kgrp * 4 + b][nloc]) << (8 * b);
    *reinterpret_cast<uint32_t*>(bt + (size_t)(n0 + nloc) * DDIM + k0 + kgrp * 4) = w;
}

// ============================ GEMM kernel ============================

__global__ void __launch_bounds__(256, 2) bgemm_imma(
    const int8_t* __restrict__ A, const int8_t* __restrict__ Bt,
    const float* __restrict__ bias, float* __restrict__ out)
{
    extern __shared__ char smem[];
    const uint32_t sb = smem_u32(smem);
    const int tid  = threadIdx.x;
    const int wid  = tid >> 5, lane = tid & 31;
    const int wm   = wid & 3;          // warp M index: 4 x 32 rows
    const int wn   = wid >> 2;         // warp N index: 2 x 64 cols
    const int m0   = blockIdx.y * TILE_M;
    const int n0   = blockIdx.x * TILE_N;

    int acc[2][8][4];
#pragma unroll
    for (int i = 0; i < 2; i++)
#pragma unroll
        for (int j = 0; j < 8; j++)
#pragma unroll
            for (int k = 0; k < 4; k++) acc[i][j][k] = 0;

    // copy-thread coordinates: 1024 16B-chunks per operand tile, 4 per thread
    const int cr = tid >> 3;          // base row (0..31), rows advance by 32 per pass
    const int cc = tid & 7;           // 16B chunk in row

    // ---- pipeline prologue: stages 0,1 ----
#pragma unroll
    for (int s = 0; s < STAGES - 1; s++) {
        uint32_t sa = sb + s * STAGE_BYTES;
        uint32_t sbuf = sa + TILE_BYTES;
        int ks = s * KC;
#pragma unroll
        for (int p = 0; p < 4; p++) {
            int r = cr + p * 32;
            cp_async16(sa + swz(r, cc),   A  + (size_t)(m0 + r) * DDIM + ks + cc * 16);
            cp_async16(sbuf + swz(r, cc), Bt + (size_t)(n0 + r) * DDIM + ks + cc * 16);
        }
        CP_COMMIT();
    }

    // lane-level ldmatrix coordinates
    const int a_lrow = lane & 15;            // row within 16-row frag
    const int a_csel = lane >> 4;            // 0 = k-lo chunk, 1 = k-hi
    const int b_lrow = (lane & 7) + ((lane >> 4) << 3);  // row within 16-n block
    const int b_csel = (lane >> 3) & 1;

    // ---- mainloop: single sync per iter; loads for it+2 issued before compute ----
    for (int it = 0; it < KITERS; it++) {
        CP_WAIT(STAGES - 2);
        __syncthreads();
        // Slot (it+2)%STAGES was consumed in iter it-1, which completed before
        // the sync above -> safe to start overwriting now, before compute.
        int nx = it + STAGES - 1;
        if (nx < KITERS) {
            int sn = nx % STAGES;
            uint32_t na = sb + sn * STAGE_BYTES;
            uint32_t nb = na + TILE_BYTES;
            int ks = nx * KC;
#pragma unroll
            for (int p = 0; p < 4; p++) {
                int r = cr + p * 32;
                cp_async16(na + swz(r, cc), A  + (size_t)(m0 + r) * DDIM + ks + cc * 16);
                cp_async16(nb + swz(r, cc), Bt + (size_t)(n0 + r) * DDIM + ks + cc * 16);
            }
        }
        CP_COMMIT();

        int s = it % STAGES;
        uint32_t sa = sb + s * STAGE_BYTES;
        uint32_t sbuf = sa + TILE_BYTES;

#pragma unroll
        for (int ks = 0; ks < KC / 32; ks++) {        // 4 k32 steps
            uint32_t afr[2][4];
#pragma unroll
            for (int mf = 0; mf < 2; mf++) {
                int row = wm * 32 + mf * 16 + a_lrow;
                int ch = ks * 2 + a_csel;
                ldm_x4(afr[mf], sa + swz(row, ch));
            }
            uint32_t bfr[8][2];
#pragma unroll
            for (int np = 0; np < 4; np++) {          // 16 n-cols per x4
                int row = wn * 64 + np * 16 + b_lrow;
                int ch = ks * 2 + b_csel;
                uint32_t r4[4];
                ldm_x4(r4, sbuf + swz(row, ch));
                bfr[2 * np][0] = r4[0]; bfr[2 * np][1] = r4[1];
                bfr[2 * np + 1][0] = r4[2]; bfr[2 * np + 1][1] = r4[3];
            }
#pragma unroll
            for (int mf = 0; mf < 2; mf++)
#pragma unroll
                for (int nf = 0; nf < 8; nf++)
                    mma_s8(acc[mf][nf], afr[mf], bfr[nf]);
        }
    }

    // ---- epilogue: s32 -> f32 + bias, float2 stores ----
    const int row_base = m0 + wm * 32 + (lane >> 2);
    const int col_base = n0 + wn * 64 + 2 * (lane & 3);
#pragma unroll
    for (int nf = 0; nf < 8; nf++) {
        int c = col_base + nf * 8;
        float b0 = bias[c], b1 = bias[c + 1];
#pragma unroll
        for (int mf = 0; mf < 2; mf++) {
            int r = row_base + mf * 16;
            float2 v0 = make_float2((float)acc[mf][nf][0] + b0, (float)acc[mf][nf][1] + b1);
            *reinterpret_cast<float2*>(&out[(size_t)r * NUNITS + c]) = v0;
            float2 v1 = make_float2((float)acc[mf][nf][2] + b0, (float)acc[mf][nf][3] + b1);
            *reinterpret_cast<float2*>(&out[(size_t)(r + 8) * NUNITS + c]) = v1;
        }
    }
}

// ============================ Host ============================

extern "C" void kernel_launch(void* const* d_in, const int* in_sizes, int n_in,
                              void* d_out, int out_size) {
    const float* inputs = (const float*)d_in[0];
    const float* kern   = (const float*)d_in[1];
    const float* bias   = (const float*)d_in[2];
    float* out = (float*)d_out;

    void* pA = nullptr; void* pB = nullptr;
    cudaGetSymbolAddress(&pA, g_A);
    cudaGetSymbolAddress(&pB, g_B);

    // 1) sign-convert A: fp32 -> int8 +-1
    int groups = (BDIM * DDIM) / 16;
    sign_a_kernel<<<groups / 256, 256>>>((const float4*)inputs, (int4*)pA);

    // 2) sign-convert + transpose kernel -> Bt [N, K]
    dim3 tb(32, 8), tg(NUNITS / 32, DDIM / 32);
    sign_bt_kernel<<<tg, tb>>>(kern, (int8_t*)pB);

    // 3) GEMM (2 CTAs/SM)
    cudaFuncSetAttribute(bgemm_imma, cudaFuncAttributeMaxDynamicSharedMemorySize, SMEM_TOTAL);
    dim3 grid(NUNITS / TILE_N, BDIM / TILE_M);   // (16, 64)
    bgemm_imma<<<grid, 256, SMEM_TOTAL>>>((const int8_t*)pA, (const int8_t*)pB, bias, out);
}

// round 4
// speedup vs baseline: 1.8766x; 1.8766x over previous
#include <cuda_runtime.h>
#include <cstdint>

// Problem shape
#define BDIM   8192
#define DDIM   2048
#define NUNITS 2048
#define KW     64          // 2048 bits = 64 u32 words per row

// Packed sign bits, tiled for the GEMM: tile t holds 128 rows,
// layout [tile][j=0..63][rowInTile=0..127]  (word-transposed within tile)
__device__ __align__(128) uint32_t g_Abits[(size_t)(BDIM / 128) * KW * 128];   // 2 MB
__device__ __align__(128) uint32_t g_Bbits[(size_t)(NUNITS / 128) * KW * 128]; // 512 KB

// ============================ Pack kernels ============================

// inputs [B, D] fp32 -> bit words via ballot. One word (m, j) per warp-step.
// bit k of word j = (inputs[m][j*32+k] < 0)
__global__ void pack_a_kernel(const float* __restrict__ in, uint32_t* __restrict__ bits) {
    int lane = threadIdx.x & 31;
    int warp = (blockIdx.x * blockDim.x + threadIdx.x) >> 5;   // global warp id
    // each warp packs 4 words
#pragma unroll
    for (int s = 0; s < 4; s++) {
        int w = warp * 4 + s;                 // word index 0 .. B*KW-1
        int m = w >> 6;                       // row
        int j = w & 63;                       // word within row
        float v = in[(size_t)m * DDIM + j * 32 + lane];
        uint32_t word = __ballot_sync(0xFFFFFFFFu, v < 0.0f);
        if (lane == 0)
            bits[(size_t)(m >> 7) * (KW * 128) + j * 128 + (m & 127)] = word;
    }
}

// kernel [D, UNITS] fp32 row-major -> transposed bit words.
// bit k of word (n, j) = (kern[j*32+k][n] < 0)
__global__ void pack_b_kernel(const float* __restrict__ kern, uint32_t* __restrict__ bits) {
    __shared__ uint8_t tile[32][33];          // [k][n]
    int n0 = blockIdx.x * 32;
    int k0 = blockIdx.y * 32;                 // j = blockIdx.y
    int tx = threadIdx.x, ty = threadIdx.y;   // (32, 8)
#pragma unroll
    for (int s = 0; s < 4; s++) {
        int kk = ty + s * 8;
        float v = kern[(size_t)(k0 + kk) * NUNITS + n0 + tx];
        tile[kk][tx] = (v < 0.0f) ? 1 : 0;
    }
    __syncthreads();
    int wid = (ty * 32 + tx) >> 5;            // 0..7
    int lane = tx;                            // == lane id since blockDim.x=32
#pragma unroll
    for (int s = 0; s < 4; s++) {
        int nl = wid * 4 + s;                 // 0..31
        uint32_t word = __ballot_sync(0xFFFFFFFFu, tile[lane][nl] != 0);
        if (lane == 0) {
            int n = n0 + nl;
            bits[(size_t)(n >> 7) * (KW * 128) + blockIdx.y * 128 + (n & 127)] = word;
        }
    }
}

// ============================ popcount GEMM ============================
// out[m][n] = 2048 - 2 * sum_j popc(A[m][j] ^ B[n][j]) + bias[n]

__global__ void __launch_bounds__(256, 2) popc_gemm(
    const uint32_t* __restrict__ Ab, const uint32_t* __restrict__ Bb,
    const float* __restrict__ bias, float* __restrict__ out)
{
    extern __shared__ uint32_t smem[];        // [0..8192) A tile, [8192..16384) B tile
    uint32_t* Asm = smem;
    uint32_t* Bsm = smem + KW * 128;

    const int tid = threadIdx.x;
    const int nblk = blockIdx.x, mblk = blockIdx.y;

    // one-shot cooperative copy: 2048 uint4 per tile, 8 per thread
    {
        const uint4* gA = (const uint4*)(Ab + (size_t)mblk * (KW * 128));
        const uint4* gB = (const uint4*)(Bb + (size_t)nblk * (KW * 128));
        uint4* sA = (uint4*)Asm;
        uint4* sB = (uint4*)Bsm;
#pragma unroll
        for (int i = 0; i < 8; i++) {
            sA[tid + i * 256] = gA[tid + i * 256];
            sB[tid + i * 256] = gB[tid + i * 256];
        }
    }
    __syncthreads();

    const int tx = tid & 15;                  // n sub-block
    const int ty = tid >> 4;                  // m sub-block

    int acc[8][8];
#pragma unroll
    for (int i = 0; i < 8; i++)
#pragma unroll
        for (int k = 0; k < 8; k++) acc[i][k] = 0;

#pragma unroll 4
    for (int j = 0; j < KW; j++) {
        uint32_t a[8], b[8];
        *(uint4*)&a[0] = *(const uint4*)&Asm[j * 128 + ty * 8];
        *(uint4*)&a[4] = *(const uint4*)&Asm[j * 128 + ty * 8 + 4];
        *(uint4*)&b[0] = *(const uint4*)&Bsm[j * 128 + tx * 8];
        *(uint4*)&b[4] = *(const uint4*)&Bsm[j * 128 + tx * 8 + 4];
#pragma unroll
        for (int mi = 0; mi < 8; mi++)
#pragma unroll
            for (int ni = 0; ni < 8; ni++)
                acc[mi][ni] += __popc(a[mi] ^ b[ni]);
    }

    // epilogue: val = 2048 - 2*acc + bias
    const int n0 = nblk * 128 + tx * 8;
    float bl[8];
    *(float4*)&bl[0] = *(const float4*)&bias[n0];
    *(float4*)&bl[4] = *(const float4*)&bias[n0 + 4];
#pragma unroll
    for (int i = 0; i < 8; i++) bl[i] += 2048.0f;

#pragma unroll
    for (int mi = 0; mi < 8; mi++) {
        size_t row = (size_t)(mblk * 128 + ty * 8 + mi) * NUNITS + n0;
        float4 v0, v1;
        v0.x = fmaf(-2.0f, (float)acc[mi][0], bl[0]);
        v0.y = fmaf(-2.0f, (float)acc[mi][1], bl[1]);
        v0.z = fmaf(-2.0f, (float)acc[mi][2], bl[2]);
        v0.w = fmaf(-2.0f, (float)acc[mi][3], bl[3]);
        v1.x = fmaf(-2.0f, (float)acc[mi][4], bl[4]);
        v1.y = fmaf(-2.0f, (float)acc[mi][5], bl[5]);
        v1.z = fmaf(-2.0f, (float)acc[mi][6], bl[6]);
        v1.w = fmaf(-2.0f, (float)acc[mi][7], bl[7]);
        *(float4*)&out[row]     = v0;
        *(float4*)&out[row + 4] = v1;
    }
}

// ============================ Host ============================

#define GEMM_SMEM (2 * KW * 128 * 4)   // 64 KB

extern "C" void kernel_launch(void* const* d_in, const int* in_sizes, int n_in,
                              void* d_out, int out_size) {
    const float* inputs = (const float*)d_in[0];
    const float* kern   = (const float*)d_in[1];
    const float* bias   = (const float*)d_in[2];
    float* out = (float*)d_out;

    void* pA = nullptr; void* pB = nullptr;
    cudaGetSymbolAddress(&pA, g_Abits);
    cudaGetSymbolAddress(&pB, g_Bbits);

    // 1) pack A: 8192*64 = 524288 words, 4 per warp, 8 warps per block
    {
        int words = BDIM * KW;
        int blocks = words / (4 * 8);          // 16384
        pack_a_kernel<<<blocks, 256>>>(inputs, (uint32_t*)pA);
    }

    // 2) pack + transpose B
    {
        dim3 tb(32, 8), tg(NUNITS / 32, DDIM / 32);   // (64, 64)
        pack_b_kernel<<<tg, tb>>>(kern, (uint32_t*)pB);
    }

    // 3) popcount GEMM
    cudaFuncSetAttribute(popc_gemm, cudaFuncAttributeMaxDynamicSharedMemorySize, GEMM_SMEM);
    dim3 grid(NUNITS / 128, BDIM / 128);       // (16, 64)
    popc_gemm<<<grid, 256, GEMM_SMEM>>>((const uint32_t*)pA, (const uint32_t*)pB, bias, out);
}

// round 5
// speedup vs baseline: 2.1474x; 1.1443x over previous
#include <cuda_runtime.h>
#include <cstdint>

// Problem shape
#define BDIM   8192
#define DDIM   2048
#define NUNITS 2048
#define KW     64          // 2048 bits = 64 u32 words per row

// Packed sign bits, tiled: tile t holds 128 rows, layout [tile][j][rowInTile]
__device__ __align__(128) uint32_t g_Abits[(size_t)(BDIM / 128) * KW * 128];   // 2 MB
__device__ __align__(128) uint32_t g_Bbits[(size_t)(NUNITS / 128) * KW * 128]; // 512 KB

// ============================ Pack kernels ============================

__global__ void pack_a_kernel(const float* __restrict__ in, uint32_t* __restrict__ bits) {
    int lane = threadIdx.x & 31;
    int warp = (blockIdx.x * blockDim.x + threadIdx.x) >> 5;
#pragma unroll
    for (int s = 0; s < 4; s++) {
        int w = warp * 4 + s;                 // word index
        int m = w >> 6;
        int j = w & 63;
        float v = in[(size_t)m * DDIM + j * 32 + lane];
        uint32_t word = __ballot_sync(0xFFFFFFFFu, v < 0.0f);
        if (lane == 0)
            bits[(size_t)(m >> 7) * (KW * 128) + j * 128 + (m & 127)] = word;
    }
}

__global__ void pack_b_kernel(const float* __restrict__ kern, uint32_t* __restrict__ bits) {
    __shared__ uint8_t tile[32][33];          // [k][n]
    int n0 = blockIdx.x * 32;
    int k0 = blockIdx.y * 32;
    int tx = threadIdx.x, ty = threadIdx.y;   // (32, 8)
#pragma unroll
    for (int s = 0; s < 4; s++) {
        int kk = ty + s * 8;
        float v = kern[(size_t)(k0 + kk) * NUNITS + n0 + tx];
        tile[kk][tx] = (v < 0.0f) ? 1 : 0;
    }
    __syncthreads();
    int wid = (ty * 32 + tx) >> 5;
    int lane = tx;
#pragma unroll
    for (int s = 0; s < 4; s++) {
        int nl = wid * 4 + s;
        uint32_t word = __ballot_sync(0xFFFFFFFFu, tile[lane][nl] != 0);
        if (lane == 0) {
            int n = n0 + nl;
            bits[(size_t)(n >> 7) * (KW * 128) + blockIdx.y * 128 + (n & 127)] = word;
        }
    }
}

// ============================ popcount GEMM (3:2 CSA) ============================
// out[m][n] = 2048 - 2 * sum_j popc(A[m][j] ^ B[n][j]) + bias[n]
// CSA: for word triples, popc(x0)+popc(x1)+popc(x2) = popc(x0^x1^x2) + 2*popc(maj(x0,x1,x2))

__global__ void __launch_bounds__(256) popc_gemm(
    const uint32_t* __restrict__ Ab, const uint32_t* __restrict__ Bb,
    const float* __restrict__ bias, float* __restrict__ out)
{
    extern __shared__ uint32_t smem[];        // A tile 8192 words, B tile 8192 words
    uint32_t* Asm = smem;
    uint32_t* Bsm = smem + KW * 128;

    const int tid = threadIdx.x;
    const int nblk = blockIdx.x, mblk = blockIdx.y;

    // one-shot cooperative copy: 2048 uint4 per tile, 8 per thread
    {
        const uint4* gA = (const uint4*)(Ab + (size_t)mblk * (KW * 128));
        const uint4* gB = (const uint4*)(Bb + (size_t)nblk * (KW * 128));
        uint4* sA = (uint4*)Asm;
        uint4* sB = (uint4*)Bsm;
#pragma unroll
        for (int i = 0; i < 8; i++) {
            sA[tid + i * 256] = gA[tid + i * 256];
            sB[tid + i * 256] = gB[tid + i * 256];
        }
    }
    __syncthreads();

    const int tx = tid & 15;                  // n sub-block
    const int ty = tid >> 4;                  // m sub-block

    int acc[8][8];
#pragma unroll
    for (int i = 0; i < 8; i++)
#pragma unroll
        for (int k = 0; k < 8; k++) acc[i][k] = 0;

    // 21 groups of 3 words (j = 0..62), CSA-compressed
#pragma unroll 3
    for (int jg = 0; jg < 21; jg++) {
        uint32_t a0[8], a1[8], a2[8], b0[8], b1[8], b2[8];
        const uint32_t* Ap = &Asm[(jg * 3) * 128 + ty * 8];
        const uint32_t* Bp = &Bsm[(jg * 3) * 128 + tx * 8];
        *(uint4*)&a0[0] = *(const uint4*)&Ap[0];   *(uint4*)&a0[4] = *(const uint4*)&Ap[4];
        *(uint4*)&a1[0] = *(const uint4*)&Ap[128]; *(uint4*)&a1[4] = *(const uint4*)&Ap[132];
        *(uint4*)&a2[0] = *(const uint4*)&Ap[256]; *(uint4*)&a2[4] = *(const uint4*)&Ap[260];
        *(uint4*)&b0[0] = *(const uint4*)&Bp[0];   *(uint4*)&b0[4] = *(const uint4*)&Bp[4];
        *(uint4*)&b1[0] = *(const uint4*)&Bp[128]; *(uint4*)&b1[4] = *(const uint4*)&Bp[132];
        *(uint4*)&b2[0] = *(const uint4*)&Bp[256]; *(uint4*)&b2[4] = *(const uint4*)&Bp[260];
#pragma unroll
        for (int mi = 0; mi < 8; mi++) {
#pragma unroll
            for (int ni = 0; ni < 8; ni++) {
                uint32_t x0 = a0[mi] ^ b0[ni];
                uint32_t x1 = a1[mi] ^ b1[ni];
                uint32_t x2 = a2[mi] ^ b2[ni];
                uint32_t s = x0 ^ x1 ^ x2;                      // LOP3 0x96
                uint32_t c = (x0 & x1) | (x2 & (x0 | x1));      // LOP3 0xE8 (majority)
                acc[mi][ni] += __popc(s) + 2 * __popc(c);
            }
        }
    }
    // leftover word j = 63
    {
        uint32_t a[8], b[8];
        const uint32_t* Ap = &Asm[63 * 128 + ty * 8];
        const uint32_t* Bp = &Bsm[63 * 128 + tx * 8];
        *(uint4*)&a[0] = *(const uint4*)&Ap[0]; *(uint4*)&a[4] = *(const uint4*)&Ap[4];
        *(uint4*)&b[0] = *(const uint4*)&Bp[0]; *(uint4*)&b[4] = *(const uint4*)&Bp[4];
#pragma unroll
        for (int mi = 0; mi < 8; mi++)
#pragma unroll
            for (int ni = 0; ni < 8; ni++)
                acc[mi][ni] += __popc(a[mi] ^ b[ni]);
    }

    // epilogue: val = 2048 - 2*acc + bias
    const int n0 = nblk * 128 + tx * 8;
    float bl[8];
    *(float4*)&bl[0] = *(const float4*)&bias[n0];
    *(float4*)&bl[4] = *(const float4*)&bias[n0 + 4];
#pragma unroll
    for (int i = 0; i < 8; i++) bl[i] += 2048.0f;

#pragma unroll
    for (int mi = 0; mi < 8; mi++) {
        size_t row = (size_t)(mblk * 128 + ty * 8 + mi) * NUNITS + n0;
        float4 v0, v1;
        v0.x = fmaf(-2.0f, (float)acc[mi][0], bl[0]);
        v0.y = fmaf(-2.0f, (float)acc[mi][1], bl[1]);
        v0.z = fmaf(-2.0f, (float)acc[mi][2], bl[2]);
        v0.w = fmaf(-2.0f, (float)acc[mi][3], bl[3]);
        v1.x = fmaf(-2.0f, (float)acc[mi][4], bl[4]);
        v1.y = fmaf(-2.0f, (float)acc[mi][5], bl[5]);
        v1.z = fmaf(-2.0f, (float)acc[mi][6], bl[6]);
        v1.w = fmaf(-2.0f, (float)acc[mi][7], bl[7]);
        *(float4*)&out[row]     = v0;
        *(float4*)&out[row + 4] = v1;
    }
}

// ============================ Host ============================

#define GEMM_SMEM (2 * KW * 128 * 4)   // 64 KB

extern "C" void kernel_launch(void* const* d_in, const int* in_sizes, int n_in,
                              void* d_out, int out_size) {
    const float* inputs = (const float*)d_in[0];
    const float* kern   = (const float*)d_in[1];
    const float* bias   = (const float*)d_in[2];
    float* out = (float*)d_out;

    void* pA = nullptr; void* pB = nullptr;
    cudaGetSymbolAddress(&pA, g_Abits);
    cudaGetSymbolAddress(&pB, g_Bbits);

    // 1) pack A
    {
        int words = BDIM * KW;
        int blocks = words / (4 * 8);          // 16384
        pack_a_kernel<<<blocks, 256>>>(inputs, (uint32_t*)pA);
    }
    // 2) pack + transpose B
    {
        dim3 tb(32, 8), tg(NUNITS / 32, DDIM / 32);
        pack_b_kernel<<<tg, tb>>>(kern, (uint32_t*)pB);
    }
    // 3) CSA popcount GEMM
    cudaFuncSetAttribute(popc_gemm, cudaFuncAttributeMaxDynamicSharedMemorySize, GEMM_SMEM);
    dim3 grid(NUNITS / 128, BDIM / 128);       // (16, 64)
    popc_gemm<<<grid, 256, GEMM_SMEM>>>((const uint32_t*)pA, (const uint32_t*)pB, bias, out);
}